// round 15
// baseline (speedup 1.0000x reference)
#include <cuda_runtime.h>

#define B_ 128
#define N_ 1024
#define E_ 16384
#define ENTITY_ 100000
#define HID_ 100
#define G3 300

// Scratch (static __device__ per harness rules; no runtime allocation)
__device__ float g_seq[B_ * N_ * HID_];      // spmm(emb[nbr])      (52MB)
__device__ float g_Wc[HID_ * G3];            // gcn_w @ w_ih^T  [100][300] k-major
__device__ float g_bc[G3];                   // w_ih @ gcn_b + b_ih
__device__ int   g_soff[B_ * (N_ + 1)];
__device__ int   g_scol[B_ * E_];
__device__ float g_sval[B_ * E_];

typedef unsigned long long u64;
typedef unsigned int u32;

__device__ __forceinline__ void ffma2(u64 &acc, u64 a, u64 b) {
    asm("fma.rn.f32x2 %0, %1, %2, %0;" : "+l"(acc) : "l"(a), "l"(b));
}
__device__ __forceinline__ u64 pk2(float lo, float hi) {
    u64 r; asm("mov.b64 %0, {%1, %2};" : "=l"(r) : "f"(lo), "f"(hi)); return r;
}
__device__ __forceinline__ float sum2(u64 v) {
    float lo, hi; asm("mov.b64 {%0, %1}, %2;" : "=f"(lo), "=f"(hi) : "l"(v)); return lo + hi;
}
__device__ __forceinline__ u32 f2tf(float x) {
    u32 r; asm("cvt.rna.tf32.f32 %0, %1;" : "=r"(r) : "f"(x)); return r;
}
__device__ __forceinline__ float tanhapx(float x) {
    float r; asm("tanh.approx.f32 %0, %1;" : "=f"(r) : "f"(x)); return r;
}
__device__ __forceinline__ void mma1688(float c[4], u32 a0, u32 a1, u32 a2, u32 a3,
                                        u32 b0, u32 b1) {
    asm("mma.sync.aligned.m16n8k8.row.col.f32.tf32.tf32.f32 "
        "{%0,%1,%2,%3}, {%4,%5,%6,%7}, {%8,%9}, {%0,%1,%2,%3};"
        : "+f"(c[0]), "+f"(c[1]), "+f"(c[2]), "+f"(c[3])
        : "r"(a0), "r"(a1), "r"(a2), "r"(a3), "r"(b0), "r"(b1));
}

__device__ __forceinline__ int kidx(int k) {   // paired index within a 104-k row
    return ((k >> 3) << 3) + ((k & 3) << 1) + ((k & 7) >> 2);
}

// ---------------------------------------------------------------------------
// K0: fold the GCN weights through the GRU input projection (fp32).
// ---------------------------------------------------------------------------
__global__ __launch_bounds__(G3) void k0_fold(const float* __restrict__ gcn_w,
                                              const float* __restrict__ gcn_b,
                                              const float* __restrict__ w_ih,
                                              const float* __restrict__ b_ih) {
    __shared__ float xs[HID_];
    int j = threadIdx.x;
    int e = blockIdx.x;
    const float* src = (e < HID_) ? (gcn_w + e * HID_) : gcn_b;
    if (j < HID_) xs[j] = src[j];
    __syncthreads();
    float acc = (e < HID_) ? 0.f : b_ih[j];
    const float* wr = w_ih + j * HID_;
    #pragma unroll
    for (int h = 0; h < HID_; h++) acc += xs[h] * wr[h];
    if (e < HID_) g_Wc[e * G3 + j] = acc;
    else          g_bc[j] = acc;
}

// ---------------------------------------------------------------------------
// K2: per-batch counting sort of edges by row (histogram + scan + scatter)
// ---------------------------------------------------------------------------
__global__ __launch_bounds__(1024) void k2_sort(const int* __restrict__ row,
                                                const int* __restrict__ col,
                                                const float* __restrict__ val) {
    __shared__ int bins[N_];
    __shared__ int sA[N_];
    int b = blockIdx.x, tid = threadIdx.x;
    bins[tid] = 0;
    __syncthreads();
    const int* rb = row + b * E_;
    const int* cb = col + b * E_;
    const float* vb = val + b * E_;
    for (int e = tid; e < E_; e += 1024) atomicAdd(&bins[rb[e]], 1);
    __syncthreads();
    int cnt = bins[tid];
    sA[tid] = cnt;
    __syncthreads();
    for (int off = 1; off < N_; off <<= 1) {
        int t = (tid >= off) ? sA[tid - off] : 0;
        __syncthreads();
        sA[tid] += t;
        __syncthreads();
    }
    int excl = sA[tid] - cnt;
    g_soff[b * (N_ + 1) + tid] = excl;
    if (tid == 0) g_soff[b * (N_ + 1) + N_] = E_;
    bins[tid] = excl;
    __syncthreads();
    for (int e = tid; e < E_; e += 1024) {
        int r = rb[e];
        int pos = atomicAdd(&bins[r], 1);
        g_scol[b * E_ + pos] = cb[e];
        g_sval[b * E_ + pos] = vb[e];
    }
}

// ---------------------------------------------------------------------------
// K3: seq[b,r,:] = sum_e val * emb[neighbors[b, col_e], :]   (pure spmm)
// ---------------------------------------------------------------------------
__global__ __launch_bounds__(256) void k3_agg(const float* __restrict__ emb,
                                              const int* __restrict__ nbr) {
    int b = blockIdx.x;
    int rbase = blockIdx.y * 64;
    int warp = threadIdx.x >> 5, lane = threadIdx.x & 31;
    const int* sc = g_scol + b * E_;
    const float* sv = g_sval + b * E_;
    const int* nb = nbr + b * N_;
    bool ld = lane < 25;
    for (int r = rbase + warp; r < rbase + 64; r += 8) {
        int beg = g_soff[b * (N_ + 1) + r], end = g_soff[b * (N_ + 1) + r + 1];
        float4 acc0 = make_float4(0.f, 0.f, 0.f, 0.f);
        float4 acc1 = make_float4(0.f, 0.f, 0.f, 0.f);
        for (int ch = beg; ch < end; ch += 32) {
            int e = ch + lane;
            int cc = 0; float vv = 0.f;
            if (e < end) { cc = sc[e]; vv = sv[e]; }
            int ent = nb[cc];
            int cnt = min(32, end - ch);
            int i = 0;
            for (; i + 3 < cnt; i += 4) {
                int e0 = __shfl_sync(0xffffffffu, ent, i);
                int e1 = __shfl_sync(0xffffffffu, ent, i + 1);
                int e2 = __shfl_sync(0xffffffffu, ent, i + 2);
                int e3 = __shfl_sync(0xffffffffu, ent, i + 3);
                float v0 = __shfl_sync(0xffffffffu, vv, i);
                float v1 = __shfl_sync(0xffffffffu, vv, i + 1);
                float v2 = __shfl_sync(0xffffffffu, vv, i + 2);
                float v3 = __shfl_sync(0xffffffffu, vv, i + 3);
                if (ld) {
                    float4 x0 = *(const float4*)(emb + (size_t)e0 * HID_ + 4 * lane);
                    float4 x1 = *(const float4*)(emb + (size_t)e1 * HID_ + 4 * lane);
                    float4 x2 = *(const float4*)(emb + (size_t)e2 * HID_ + 4 * lane);
                    float4 x3 = *(const float4*)(emb + (size_t)e3 * HID_ + 4 * lane);
                    acc0.x += v0 * x0.x; acc0.y += v0 * x0.y; acc0.z += v0 * x0.z; acc0.w += v0 * x0.w;
                    acc1.x += v1 * x1.x; acc1.y += v1 * x1.y; acc1.z += v1 * x1.z; acc1.w += v1 * x1.w;
                    acc0.x += v2 * x2.x; acc0.y += v2 * x2.y; acc0.z += v2 * x2.z; acc0.w += v2 * x2.w;
                    acc1.x += v3 * x3.x; acc1.y += v3 * x3.y; acc1.z += v3 * x3.z; acc1.w += v3 * x3.w;
                }
            }
            for (; i < cnt; i++) {
                int e0 = __shfl_sync(0xffffffffu, ent, i);
                float v0 = __shfl_sync(0xffffffffu, vv, i);
                if (ld) {
                    float4 x0 = *(const float4*)(emb + (size_t)e0 * HID_ + 4 * lane);
                    acc0.x += v0 * x0.x; acc0.y += v0 * x0.y; acc0.z += v0 * x0.z; acc0.w += v0 * x0.w;
                }
            }
        }
        if (ld) {
            float4 o;
            o.x = acc0.x + acc1.x;
            o.y = acc0.y + acc1.y;
            o.z = acc0.z + acc1.z;
            o.w = acc0.w + acc1.w;
            *(float4*)(g_seq + (size_t)(b * N_ + r) * HID_ + 4 * lane) = o;
        }
    }
}

// ---------------------------------------------------------------------------
// K45: fused GX-GEMM + GRU recurrence. One block (800 thr = 25 warps) per
// batch. Chunk-gemm (warps 0-18) unchanged. Recurrence: thread = (j<100,
// k-eighth q8=tid&7) holds w_hh rows {j, j+100, j+200} over its eighth ->
// 3 gate partials for ONE hidden unit. The 8 eighths of j sit in 8 adjacent
// lanes: 3-level shfl_xor butterfly reduces in-warp (no ps smem, no second
// phase); lane q8=0 computes the full activation for j and writes h[j].
// ONE __syncthreads per step (h publish; WAR covered by same barrier).
// h in eighth-padded hq[2][8][20]. HW tanh.approx gates.
// ---------------------------------------------------------------------------
#define K45_SMEM ((304 * 104 + 32 * 104) * 4 + (32 * 304 + 304 + 320) * 4)

__global__ __launch_bounds__(800) void k45_gru(const float* __restrict__ w_hh,
                                               const float* __restrict__ b_hh,
                                               const float* __restrict__ fc1_w,
                                               const float* __restrict__ fc1_b,
                                               float* __restrict__ out) {
    extern __shared__ u32 smem[];
    u32* Wcs = smem;                          // [304][104] tf32 paired
    u32* Xs  = smem + 304 * 104;              // [32][104]  tf32 paired
    float* fb = (float*)smem;
    float* GXc  = fb + 304 * 104 + 32 * 104;  // [32][304]
    float* bcs  = GXc + 32 * 304;             // [304]
    float* hq   = bcs + 304;                  // [2][8][20] eighth-padded h

    int b = blockIdx.x, tid = threadIdx.x;
    int w = tid >> 5, lane = tid & 31;
    int g = lane >> 2, tig = lane & 3;
    int col0 = w * 16;                        // chunk-gemm warp cols (w<19)

    // recurrence mapping: tid = j*8 + q8
    int q8 = tid & 7;                         // k-eighth: k in [13q8, 13q8+13)
    int j  = tid >> 3;                        // hidden unit, always < 100
    bool win = (q8 == 0);

    // weights: rows j (r), j+100 (z), j+200 (n) over this thread's eighth
    u64 w2[3][7];
    #pragma unroll
    for (int gg = 0; gg < 3; gg++) {
        const float* wr = w_hh + (j + gg * HID_) * HID_;
        #pragma unroll
        for (int p = 0; p < 7; p++) {
            int k = 13 * q8 + 2 * p;
            float lo = (k < HID_) ? wr[k] : 0.f;
            float hi = (2 * p + 1 < 13 && k + 1 < HID_) ? wr[k + 1] : 0.f;
            w2[gg][p] = pk2(lo, hi);
        }
    }
    float br = b_hh[j], bz = b_hh[HID_ + j], bn = b_hh[2 * HID_ + j];
    int dh = j / 13, mh = j - dh * 13;        // h[j] slot in eighth-padded layout

    for (int i = tid; i < 320; i += 800) hq[i] = 0.f;   // zero h + pads

    // Stage Wc (k-major [100][300]) as paired tf32
    for (int i = tid; i < 304 * 104; i += 800) {
        int n = i / 104, k = i % 104;
        float v = (n < G3 && k < HID_) ? g_Wc[k * G3 + n] : 0.f;
        Wcs[n * 104 + kidx(k)] = f2tf(v);
    }
    for (int i = tid; i < 304; i += 800)
        bcs[i] = (i < G3) ? g_bc[i] : 0.f;
    __syncthreads();

    const float4* seq4 = (const float4*)(g_seq + (size_t)b * N_ * HID_);

    for (int ch = 0; ch < 32; ch++) {
        // ---- stage X chunk (32 rows) ----
        for (int i = tid; i < 32 * 26; i += 800) {
            int m = i / 26, cc = i % 26;
            u32* rowp = Xs + m * 104;
            if (cc < 25) {
                float4 v = seq4[(size_t)(ch * 32 + m) * 25 + cc];
                int base = ((cc >> 1) << 3) + (cc & 1);
                rowp[base]     = f2tf(v.x);
                rowp[base + 2] = f2tf(v.y);
                rowp[base + 4] = f2tf(v.z);
                rowp[base + 6] = f2tf(v.w);
            } else {
                rowp[97] = 0u; rowp[99] = 0u; rowp[101] = 0u; rowp[103] = 0u;
            }
        }
        __syncthreads();

        // ---- chunk gemm: GXc = X @ Wc + bc (warps 0-18) ----
        if (w < 19) {
            #pragma unroll
            for (int mp = 0; mp < 2; mp++) {
                float cf0[4] = {0.f, 0.f, 0.f, 0.f};
                float cf1[4] = {0.f, 0.f, 0.f, 0.f};
                const u32* Xb = Xs + (mp * 16) * 104;
                #pragma unroll
                for (int ks = 0; ks < 13; ks++) {
                    int k0 = ks * 8 + 2 * tig;
                    uint2 a0 = *(const uint2*)&Xb[g * 104 + k0];
                    uint2 a1 = *(const uint2*)&Xb[(g + 8) * 104 + k0];
                    uint2 b0 = *(const uint2*)&Wcs[(col0 + g) * 104 + k0];
                    uint2 b1 = *(const uint2*)&Wcs[(col0 + 8 + g) * 104 + k0];
                    mma1688(cf0, a0.x, a1.x, a0.y, a1.y, b0.x, b0.y);
                    mma1688(cf1, a0.x, a1.x, a0.y, a1.y, b1.x, b1.y);
                }
                int r = mp * 16 + g;
                int c0 = col0 + 2 * tig;
                int c1 = col0 + 8 + 2 * tig;
                GXc[r * 304 + c0]           = cf0[0] + bcs[c0];
                GXc[r * 304 + c0 + 1]       = cf0[1] + bcs[c0 + 1];
                GXc[(r + 8) * 304 + c0]     = cf0[2] + bcs[c0];
                GXc[(r + 8) * 304 + c0 + 1] = cf0[3] + bcs[c0 + 1];
                GXc[r * 304 + c1]           = cf1[0] + bcs[c1];
                GXc[r * 304 + c1 + 1]       = cf1[1] + bcs[c1 + 1];
                GXc[(r + 8) * 304 + c1]     = cf1[2] + bcs[c1];
                GXc[(r + 8) * 304 + c1 + 1] = cf1[3] + bcs[c1 + 1];
            }
        }
        __syncthreads();   // GXc ready

        // ---- 32 recurrence steps, ONE barrier each ----
        for (int tt = 0; tt < 32; tt++) {
            int t = ch * 32 + tt;
            int cur = t & 1;
            // gate partials over this thread's eighth
            const float* hb = hq + cur * 160 + q8 * 20;
            ulonglong2 u0 = *(const ulonglong2*)(hb);
            ulonglong2 u1 = *(const ulonglong2*)(hb + 4);
            ulonglong2 u2 = *(const ulonglong2*)(hb + 8);
            ulonglong2 u3 = *(const ulonglong2*)(hb + 12);
            float svr, svz, svn;
            {
                u64 a0 = 0, a1 = 0;
                ffma2(a0, w2[0][0], u0.x); ffma2(a1, w2[0][1], u0.y);
                ffma2(a0, w2[0][2], u1.x); ffma2(a1, w2[0][3], u1.y);
                ffma2(a0, w2[0][4], u2.x); ffma2(a1, w2[0][5], u2.y);
                ffma2(a0, w2[0][6], u3.x);
                svr = sum2(a0) + sum2(a1);
            }
            {
                u64 a0 = 0, a1 = 0;
                ffma2(a0, w2[1][0], u0.x); ffma2(a1, w2[1][1], u0.y);
                ffma2(a0, w2[1][2], u1.x); ffma2(a1, w2[1][3], u1.y);
                ffma2(a0, w2[1][4], u2.x); ffma2(a1, w2[1][5], u2.y);
                ffma2(a0, w2[1][6], u3.x);
                svz = sum2(a0) + sum2(a1);
            }
            {
                u64 a0 = 0, a1 = 0;
                ffma2(a0, w2[2][0], u0.x); ffma2(a1, w2[2][1], u0.y);
                ffma2(a0, w2[2][2], u1.x); ffma2(a1, w2[2][3], u1.y);
                ffma2(a0, w2[2][4], u2.x); ffma2(a1, w2[2][5], u2.y);
                ffma2(a0, w2[2][6], u3.x);
                svn = sum2(a0) + sum2(a1);
            }
            // butterfly across the 8 eighths (lanes l^1, l^2, l^4)
            #pragma unroll
            for (int off = 1; off < 8; off <<= 1) {
                svr += __shfl_xor_sync(0xffffffffu, svr, off);
                svz += __shfl_xor_sync(0xffffffffu, svz, off);
                svn += __shfl_xor_sync(0xffffffffu, svn, off);
            }
            if (win) {
                const float* gx = GXc + tt * 304;
                float gxr = gx[j], gxz = gx[HID_ + j], gxn = gx[2 * HID_ + j];
                float r = 0.5f * tanhapx(0.5f * (gxr + svr + br)) + 0.5f;
                float z = 0.5f * tanhapx(0.5f * (gxz + svz + bz)) + 0.5f;
                float n = tanhapx(gxn + r * (svn + bn));
                float hcur = hq[cur * 160 + dh * 20 + mh];
                hq[(cur ^ 1) * 160 + dh * 20 + mh] = (1.f - z) * n + z * hcur;
            }
            __syncthreads();                 // h(t+1) published; WAR ordered
        }
    }

    if (tid < HID_) {
        float acc = fc1_b[tid];
        const float* wr = fc1_w + tid * HID_;
        #pragma unroll
        for (int k = 0; k < HID_; k++) {
            int dq = k / 13, mq = k - dq * 13;
            acc += hq[dq * 20 + mq] * wr[k];     // final h lives in buffer 0
        }
        out[b * HID_ + tid] = fmaxf(acc, 0.f);
    }
}

// ---------------------------------------------------------------------------
extern "C" void kernel_launch(void* const* d_in, const int* in_sizes, int n_in,
                              void* d_out, int out_size) {
    const int*   neighbors = (const int*)d_in[0];
    const int*   adj_row   = (const int*)d_in[1];
    const int*   adj_col   = (const int*)d_in[2];
    const float* adj_val   = (const float*)d_in[3];
    const float* emb       = (const float*)d_in[4];
    const float* gcn_w     = (const float*)d_in[5];
    const float* gcn_b     = (const float*)d_in[6];
    const float* w_ih      = (const float*)d_in[7];
    const float* w_hh      = (const float*)d_in[8];
    const float* b_ih      = (const float*)d_in[9];
    const float* b_hh      = (const float*)d_in[10];
    const float* fc1_w     = (const float*)d_in[11];
    const float* fc1_b     = (const float*)d_in[12];
    float* out = (float*)d_out;

    cudaFuncSetAttribute(k45_gru, cudaFuncAttributeMaxDynamicSharedMemorySize, K45_SMEM);

    // K0: fold gcn_w/gcn_b through w_ih/b_ih  -> g_Wc, g_bc
    k0_fold<<<HID_ + 1, G3>>>(gcn_w, gcn_b, w_ih, b_ih);
    // K2: sort edges by row
    k2_sort<<<B_, 1024>>>(adj_row, adj_col, adj_val);
    // K3: pure spmm over raw embeddings
    k3_agg <<<dim3(B_, 16), 256>>>(emb, neighbors);
    // K45: fused GX-gemm + GRU recurrence + FC
    k45_gru<<<B_, 800, K45_SMEM>>>(w_hh, b_hh, fc1_w, fc1_b, out);
}

// round 16
// speedup vs baseline: 1.0491x; 1.0491x over previous
#include <cuda_runtime.h>

#define B_ 128
#define N_ 1024
#define E_ 16384
#define ENTITY_ 100000
#define HID_ 100
#define G3 300

// Scratch (static __device__ per harness rules; no runtime allocation)
__device__ float g_seq[B_ * N_ * HID_];      // spmm(emb[nbr])      (52MB)
__device__ float g_Wc[HID_ * G3];            // gcn_w @ w_ih^T  [100][300] k-major
__device__ float g_bc[G3];                   // w_ih @ gcn_b + b_ih
__device__ int   g_soff[B_ * (N_ + 1)];
__device__ int   g_scol[B_ * E_];
__device__ float g_sval[B_ * E_];

typedef unsigned long long u64;
typedef unsigned int u32;

__device__ __forceinline__ void ffma2(u64 &acc, u64 a, u64 b) {
    asm("fma.rn.f32x2 %0, %1, %2, %0;" : "+l"(acc) : "l"(a), "l"(b));
}
__device__ __forceinline__ u64 pk2(float lo, float hi) {
    u64 r; asm("mov.b64 %0, {%1, %2};" : "=l"(r) : "f"(lo), "f"(hi)); return r;
}
__device__ __forceinline__ float sum2(u64 v) {
    float lo, hi; asm("mov.b64 {%0, %1}, %2;" : "=f"(lo), "=f"(hi) : "l"(v)); return lo + hi;
}
__device__ __forceinline__ u32 f2tf(float x) {
    u32 r; asm("cvt.rna.tf32.f32 %0, %1;" : "=r"(r) : "f"(x)); return r;
}
__device__ __forceinline__ float tanhapx(float x) {
    float r; asm("tanh.approx.f32 %0, %1;" : "=f"(r) : "f"(x)); return r;
}
__device__ __forceinline__ void mma1688(float c[4], u32 a0, u32 a1, u32 a2, u32 a3,
                                        u32 b0, u32 b1) {
    asm("mma.sync.aligned.m16n8k8.row.col.f32.tf32.tf32.f32 "
        "{%0,%1,%2,%3}, {%4,%5,%6,%7}, {%8,%9}, {%0,%1,%2,%3};"
        : "+f"(c[0]), "+f"(c[1]), "+f"(c[2]), "+f"(c[3])
        : "r"(a0), "r"(a1), "r"(a2), "r"(a3), "r"(b0), "r"(b1));
}

__device__ __forceinline__ int kidx(int k) {   // paired index within a 104-k row
    return ((k >> 3) << 3) + ((k & 3) << 1) + ((k & 7) >> 2);
}

// ---------------------------------------------------------------------------
// K0: fold the GCN weights through the GRU input projection (fp32).
// ---------------------------------------------------------------------------
__global__ __launch_bounds__(G3) void k0_fold(const float* __restrict__ gcn_w,
                                              const float* __restrict__ gcn_b,
                                              const float* __restrict__ w_ih,
                                              const float* __restrict__ b_ih) {
    __shared__ float xs[HID_];
    int j = threadIdx.x;
    int e = blockIdx.x;
    const float* src = (e < HID_) ? (gcn_w + e * HID_) : gcn_b;
    if (j < HID_) xs[j] = src[j];
    __syncthreads();
    float acc = (e < HID_) ? 0.f : b_ih[j];
    const float* wr = w_ih + j * HID_;
    #pragma unroll
    for (int h = 0; h < HID_; h++) acc += xs[h] * wr[h];
    if (e < HID_) g_Wc[e * G3 + j] = acc;
    else          g_bc[j] = acc;
}

// ---------------------------------------------------------------------------
// K2: per-batch counting sort of edges by row (histogram + scan + scatter)
// ---------------------------------------------------------------------------
__global__ __launch_bounds__(1024) void k2_sort(const int* __restrict__ row,
                                                const int* __restrict__ col,
                                                const float* __restrict__ val) {
    __shared__ int bins[N_];
    __shared__ int sA[N_];
    int b = blockIdx.x, tid = threadIdx.x;
    bins[tid] = 0;
    __syncthreads();
    const int* rb = row + b * E_;
    const int* cb = col + b * E_;
    const float* vb = val + b * E_;
    for (int e = tid; e < E_; e += 1024) atomicAdd(&bins[rb[e]], 1);
    __syncthreads();
    int cnt = bins[tid];
    sA[tid] = cnt;
    __syncthreads();
    for (int off = 1; off < N_; off <<= 1) {
        int t = (tid >= off) ? sA[tid - off] : 0;
        __syncthreads();
        sA[tid] += t;
        __syncthreads();
    }
    int excl = sA[tid] - cnt;
    g_soff[b * (N_ + 1) + tid] = excl;
    if (tid == 0) g_soff[b * (N_ + 1) + N_] = E_;
    bins[tid] = excl;
    __syncthreads();
    for (int e = tid; e < E_; e += 1024) {
        int r = rb[e];
        int pos = atomicAdd(&bins[r], 1);
        g_scol[b * E_ + pos] = cb[e];
        g_sval[b * E_ + pos] = vb[e];
    }
}

// ---------------------------------------------------------------------------
// K3: seq[b,r,:] = sum_e val * emb[neighbors[b, col_e], :]   (pure spmm)
// ---------------------------------------------------------------------------
__global__ __launch_bounds__(256) void k3_agg(const float* __restrict__ emb,
                                              const int* __restrict__ nbr) {
    int b = blockIdx.x;
    int rbase = blockIdx.y * 64;
    int warp = threadIdx.x >> 5, lane = threadIdx.x & 31;
    const int* sc = g_scol + b * E_;
    const float* sv = g_sval + b * E_;
    const int* nb = nbr + b * N_;
    bool ld = lane < 25;
    for (int r = rbase + warp; r < rbase + 64; r += 8) {
        int beg = g_soff[b * (N_ + 1) + r], end = g_soff[b * (N_ + 1) + r + 1];
        float4 acc0 = make_float4(0.f, 0.f, 0.f, 0.f);
        float4 acc1 = make_float4(0.f, 0.f, 0.f, 0.f);
        for (int ch = beg; ch < end; ch += 32) {
            int e = ch + lane;
            int cc = 0; float vv = 0.f;
            if (e < end) { cc = sc[e]; vv = sv[e]; }
            int ent = nb[cc];
            int cnt = min(32, end - ch);
            int i = 0;
            for (; i + 3 < cnt; i += 4) {
                int e0 = __shfl_sync(0xffffffffu, ent, i);
                int e1 = __shfl_sync(0xffffffffu, ent, i + 1);
                int e2 = __shfl_sync(0xffffffffu, ent, i + 2);
                int e3 = __shfl_sync(0xffffffffu, ent, i + 3);
                float v0 = __shfl_sync(0xffffffffu, vv, i);
                float v1 = __shfl_sync(0xffffffffu, vv, i + 1);
                float v2 = __shfl_sync(0xffffffffu, vv, i + 2);
                float v3 = __shfl_sync(0xffffffffu, vv, i + 3);
                if (ld) {
                    float4 x0 = *(const float4*)(emb + (size_t)e0 * HID_ + 4 * lane);
                    float4 x1 = *(const float4*)(emb + (size_t)e1 * HID_ + 4 * lane);
                    float4 x2 = *(const float4*)(emb + (size_t)e2 * HID_ + 4 * lane);
                    float4 x3 = *(const float4*)(emb + (size_t)e3 * HID_ + 4 * lane);
                    acc0.x += v0 * x0.x; acc0.y += v0 * x0.y; acc0.z += v0 * x0.z; acc0.w += v0 * x0.w;
                    acc1.x += v1 * x1.x; acc1.y += v1 * x1.y; acc1.z += v1 * x1.z; acc1.w += v1 * x1.w;
                    acc0.x += v2 * x2.x; acc0.y += v2 * x2.y; acc0.z += v2 * x2.z; acc0.w += v2 * x2.w;
                    acc1.x += v3 * x3.x; acc1.y += v3 * x3.y; acc1.z += v3 * x3.z; acc1.w += v3 * x3.w;
                }
            }
            for (; i < cnt; i++) {
                int e0 = __shfl_sync(0xffffffffu, ent, i);
                float v0 = __shfl_sync(0xffffffffu, vv, i);
                if (ld) {
                    float4 x0 = *(const float4*)(emb + (size_t)e0 * HID_ + 4 * lane);
                    acc0.x += v0 * x0.x; acc0.y += v0 * x0.y; acc0.z += v0 * x0.z; acc0.w += v0 * x0.w;
                }
            }
        }
        if (ld) {
            float4 o;
            o.x = acc0.x + acc1.x;
            o.y = acc0.y + acc1.y;
            o.z = acc0.z + acc1.z;
            o.w = acc0.w + acc1.w;
            *(float4*)(g_seq + (size_t)(b * N_ + r) * HID_ + 4 * lane) = o;
        }
    }
}

// ---------------------------------------------------------------------------
// K45: fused GX-GEMM + GRU recurrence [R14 structure — best known].
// One block (608 thr = 19 warps) per batch. Chunk-gemm (warps 0-18, m16n8k8).
// Recurrence: thread = (k-eighth q8=tid&7, 4 gates g0=(tid>>3)*4), 600 active;
// h in eighth-padded hq[2][8][20] -> 4 LDS.128/thread/step.
// R16 micro-opts: (1) ps transposed to gate-major ps[g][8] -> activation
// combine is 6 LDS.128 instead of 24 scalar LDS; (2) gx/hcur prefetched
// BEFORE the ps-barrier (independent of ps; hidden behind barrier wait).
// Two barriers per step. HW tanh.approx gates.
// ---------------------------------------------------------------------------
#define K45_SMEM ((304 * 104 + 32 * 104) * 4 + (32 * 304 + 304 + 320 + 304 * 8) * 4)

__global__ __launch_bounds__(608) void k45_gru(const float* __restrict__ w_hh,
                                               const float* __restrict__ b_hh,
                                               const float* __restrict__ fc1_w,
                                               const float* __restrict__ fc1_b,
                                               float* __restrict__ out) {
    extern __shared__ u32 smem[];
    u32* Wcs = smem;                          // [304][104] tf32 paired
    u32* Xs  = smem + 304 * 104;              // [32][104]  tf32 paired
    float* fb = (float*)smem;
    float* GXc  = fb + 304 * 104 + 32 * 104;  // [32][304]
    float* bcs  = GXc + 32 * 304;             // [304]
    float* hq   = bcs + 304;                  // [2][8][20] eighth-padded h
    float* ps   = hq + 320;                   // [304][8] gate-major partials

    int b = blockIdx.x, tid = threadIdx.x;
    int w = tid >> 5, lane = tid & 31;
    int g = lane >> 2, tig = lane & 3;
    int col0 = w * 16;                        // chunk-gemm warp cols (w<19)

    // recurrence mapping
    bool ghact = tid < 600;
    int q8 = tid & 7;                         // k-eighth: k in [13q8, 13q8+13)
    int g0 = (tid >> 3) << 2;                 // 4 gates g0..g0+3  (<300)

    u64 w2[4][7];
    if (ghact) {
        #pragma unroll
        for (int gg = 0; gg < 4; gg++) {
            const float* wr = w_hh + (g0 + gg) * HID_;
            #pragma unroll
            for (int p = 0; p < 7; p++) {
                int k = 13 * q8 + 2 * p;
                float lo = (k < HID_) ? wr[k] : 0.f;
                float hi = (2 * p + 1 < 13 && k + 1 < HID_) ? wr[k + 1] : 0.f;
                w2[gg][p] = pk2(lo, hi);
            }
        }
    }
    float br = 0.f, bz = 0.f, bn = 0.f;
    int dh = 0, mh = 0;
    if (tid < HID_) {
        br = b_hh[tid]; bz = b_hh[HID_ + tid]; bn = b_hh[2 * HID_ + tid];
        dh = tid / 13; mh = tid - dh * 13;
    }
    for (int i = tid; i < 320; i += 608) hq[i] = 0.f;   // zero h + pads

    // Stage Wc (k-major [100][300]) as paired tf32
    for (int i = tid; i < 304 * 104; i += 608) {
        int n = i / 104, k = i % 104;
        float v = (n < G3 && k < HID_) ? g_Wc[k * G3 + n] : 0.f;
        Wcs[n * 104 + kidx(k)] = f2tf(v);
    }
    for (int i = tid; i < 304; i += 608)
        bcs[i] = (i < G3) ? g_bc[i] : 0.f;
    __syncthreads();

    const float4* seq4 = (const float4*)(g_seq + (size_t)b * N_ * HID_);

    for (int ch = 0; ch < 32; ch++) {
        // ---- stage X chunk (32 rows) ----
        for (int i = tid; i < 32 * 26; i += 608) {
            int m = i / 26, cc = i % 26;
            u32* rowp = Xs + m * 104;
            if (cc < 25) {
                float4 v = seq4[(size_t)(ch * 32 + m) * 25 + cc];
                int base = ((cc >> 1) << 3) + (cc & 1);
                rowp[base]     = f2tf(v.x);
                rowp[base + 2] = f2tf(v.y);
                rowp[base + 4] = f2tf(v.z);
                rowp[base + 6] = f2tf(v.w);
            } else {
                rowp[97] = 0u; rowp[99] = 0u; rowp[101] = 0u; rowp[103] = 0u;
            }
        }
        __syncthreads();

        // ---- chunk gemm: GXc = X @ Wc + bc (warps 0-18) ----
        if (w < 19) {
            #pragma unroll
            for (int mp = 0; mp < 2; mp++) {
                float cf0[4] = {0.f, 0.f, 0.f, 0.f};
                float cf1[4] = {0.f, 0.f, 0.f, 0.f};
                const u32* Xb = Xs + (mp * 16) * 104;
                #pragma unroll
                for (int ks = 0; ks < 13; ks++) {
                    int k0 = ks * 8 + 2 * tig;
                    uint2 a0 = *(const uint2*)&Xb[g * 104 + k0];
                    uint2 a1 = *(const uint2*)&Xb[(g + 8) * 104 + k0];
                    uint2 b0 = *(const uint2*)&Wcs[(col0 + g) * 104 + k0];
                    uint2 b1 = *(const uint2*)&Wcs[(col0 + 8 + g) * 104 + k0];
                    mma1688(cf0, a0.x, a1.x, a0.y, a1.y, b0.x, b0.y);
                    mma1688(cf1, a0.x, a1.x, a0.y, a1.y, b1.x, b1.y);
                }
                int r = mp * 16 + g;
                int c0 = col0 + 2 * tig;
                int c1 = col0 + 8 + 2 * tig;
                GXc[r * 304 + c0]           = cf0[0] + bcs[c0];
                GXc[r * 304 + c0 + 1]       = cf0[1] + bcs[c0 + 1];
                GXc[(r + 8) * 304 + c0]     = cf0[2] + bcs[c0];
                GXc[(r + 8) * 304 + c0 + 1] = cf0[3] + bcs[c0 + 1];
                GXc[r * 304 + c1]           = cf1[0] + bcs[c1];
                GXc[r * 304 + c1 + 1]       = cf1[1] + bcs[c1 + 1];
                GXc[(r + 8) * 304 + c1]     = cf1[2] + bcs[c1];
                GXc[(r + 8) * 304 + c1 + 1] = cf1[3] + bcs[c1 + 1];
            }
        }
        __syncthreads();   // GXc ready

        // ---- 32 recurrence steps ----
        for (int tt = 0; tt < 32; tt++) {
            int t = ch * 32 + tt;
            int cur = t & 1;
            if (ghact) {
                const float* hb = hq + cur * 160 + q8 * 20;
                ulonglong2 u0 = *(const ulonglong2*)(hb);
                ulonglong2 u1 = *(const ulonglong2*)(hb + 4);
                ulonglong2 u2 = *(const ulonglong2*)(hb + 8);
                ulonglong2 u3 = *(const ulonglong2*)(hb + 12);
                #pragma unroll
                for (int gg = 0; gg < 4; gg++) {
                    u64 a0 = 0, a1 = 0;
                    ffma2(a0, w2[gg][0], u0.x);
                    ffma2(a1, w2[gg][1], u0.y);
                    ffma2(a0, w2[gg][2], u1.x);
                    ffma2(a1, w2[gg][3], u1.y);
                    ffma2(a0, w2[gg][4], u2.x);
                    ffma2(a1, w2[gg][5], u2.y);
                    ffma2(a0, w2[gg][6], u3.x);
                    ps[(g0 + gg) * 8 + q8] = sum2(a0) + sum2(a1);
                }
            }
            // prefetch activation inputs BEFORE the barrier (independent of ps)
            float gxr = 0.f, gxz = 0.f, gxn = 0.f, hcur = 0.f;
            if (tid < HID_) {
                const float* gx = GXc + tt * 304;
                gxr = gx[tid]; gxz = gx[HID_ + tid]; gxn = gx[2 * HID_ + tid];
                hcur = hq[cur * 160 + dh * 20 + mh];
            }
            __syncthreads();                 // partials ready
            if (tid < HID_) {
                float4 pr0 = *(const float4*)&ps[tid * 8];
                float4 pr1 = *(const float4*)&ps[tid * 8 + 4];
                float4 pz0 = *(const float4*)&ps[(HID_ + tid) * 8];
                float4 pz1 = *(const float4*)&ps[(HID_ + tid) * 8 + 4];
                float4 pn0 = *(const float4*)&ps[(2 * HID_ + tid) * 8];
                float4 pn1 = *(const float4*)&ps[(2 * HID_ + tid) * 8 + 4];
                float hr = ((pr0.x + pr0.y) + (pr0.z + pr0.w))
                         + ((pr1.x + pr1.y) + (pr1.z + pr1.w)) + br;
                float hz = ((pz0.x + pz0.y) + (pz0.z + pz0.w))
                         + ((pz1.x + pz1.y) + (pz1.z + pz1.w)) + bz;
                float hn = ((pn0.x + pn0.y) + (pn0.z + pn0.w))
                         + ((pn1.x + pn1.y) + (pn1.z + pn1.w)) + bn;
                float r = 0.5f * tanhapx(0.5f * (gxr + hr)) + 0.5f;
                float z = 0.5f * tanhapx(0.5f * (gxz + hz)) + 0.5f;
                float n = tanhapx(gxn + r * hn);
                hq[(cur ^ 1) * 160 + dh * 20 + mh] = (1.f - z) * n + z * hcur;
            }
            __syncthreads();                 // h(t+1) ready; ps WAR protected
        }
    }

    if (tid < HID_) {
        float acc = fc1_b[tid];
        const float* wr = fc1_w + tid * HID_;
        #pragma unroll
        for (int k = 0; k < HID_; k++) {
            int dq = k / 13, mq = k - dq * 13;
            acc += hq[dq * 20 + mq] * wr[k];     // final h lives in buffer 0
        }
        out[b * HID_ + tid] = fmaxf(acc, 0.f);
    }
}

// ---------------------------------------------------------------------------
extern "C" void kernel_launch(void* const* d_in, const int* in_sizes, int n_in,
                              void* d_out, int out_size) {
    const int*   neighbors = (const int*)d_in[0];
    const int*   adj_row   = (const int*)d_in[1];
    const int*   adj_col   = (const int*)d_in[2];
    const float* adj_val   = (const float*)d_in[3];
    const float* emb       = (const float*)d_in[4];
    const float* gcn_w     = (const float*)d_in[5];
    const float* gcn_b     = (const float*)d_in[6];
    const float* w_ih      = (const float*)d_in[7];
    const float* w_hh      = (const float*)d_in[8];
    const float* b_ih      = (const float*)d_in[9];
    const float* b_hh      = (const float*)d_in[10];
    const float* fc1_w     = (const float*)d_in[11];
    const float* fc1_b     = (const float*)d_in[12];
    float* out = (float*)d_out;

    cudaFuncSetAttribute(k45_gru, cudaFuncAttributeMaxDynamicSharedMemorySize, K45_SMEM);

    // K0: fold gcn_w/gcn_b through w_ih/b_ih  -> g_Wc, g_bc
    k0_fold<<<HID_ + 1, G3>>>(gcn_w, gcn_b, w_ih, b_ih);
    // K2: sort edges by row
    k2_sort<<<B_, 1024>>>(adj_row, adj_col, adj_val);
    // K3: pure spmm over raw embeddings
    k3_agg <<<dim3(B_, 16), 256>>>(emb, neighbors);
    // K45: fused GX-gemm + GRU recurrence + FC
    k45_gru<<<B_, 608, K45_SMEM>>>(w_hh, b_hh, fc1_w, fc1_b, out);
}